// round 2
// baseline (speedup 1.0000x reference)
#include <cuda_runtime.h>
#include <cuda_bf16.h>
#include <cstdint>
#include <cfloat>

// Problem constants
#define NPTS 32768   // candidate points per side
#define MQ   8192    // query (shortcut) points per side
#define CF   256     // feature channels

// Grid constants
#define G     64
#define G3    (G * G * G)          // 262144 cells per side
#define TOTC  (2 * G3)             // 524288 cells total
#define HCELL 0.125f
#define INVH  8.0f                 // G / 8.0
#define ORI   (-4.0f)

#define SCAN_BLK 1024
#define SCAN_NBLK (TOTC / SCAN_BLK)   // 512

// ---------------- scratch ----------------
__device__ int    g_count[TOTC];        // histogram, then scatter cursor
__device__ int    g_off[TOTC + 1];      // exclusive offsets
__device__ int    g_blksum[SCAN_NBLK];  // scan partials
__device__ float4 g_pts[2 * NPTS];      // cell-sorted points (x,y,z, idx-bits)
__device__ int    g_idx2[2][MQ];        // 2nd-NN index per query

// ---------------- helpers ----------------
__device__ __forceinline__ int cell_of(float v) {
    int c = (int)floorf((v - ORI) * INVH);
    return min(max(c, 0), G - 1);
}

// ---------------- K0: zero counts ----------------
__global__ void zero_kernel() {
    int gid = blockIdx.x * blockDim.x + threadIdx.x;
    if (gid < TOTC) g_count[gid] = 0;
    if (gid == 0) g_off[0] = 0;
}

// ---------------- K1: histogram ----------------
__global__ void hist_kernel(const float* __restrict__ src_coords,
                            const float* __restrict__ tgt_coords) {
    int u = blockIdx.x * blockDim.x + threadIdx.x;
    if (u >= 2 * NPTS) return;
    int side = u >> 15;
    int i = u & (NPTS - 1);
    const float* c = side ? tgt_coords : src_coords;
    float x = c[3 * i], y = c[3 * i + 1], z = c[3 * i + 2];
    int cell = side * G3 + (cell_of(z) * G + cell_of(y)) * G + cell_of(x);
    atomicAdd(&g_count[cell], 1);
}

// ---------------- K2a: per-block inclusive scan ----------------
__global__ void scanA_kernel() {
    __shared__ int sh[SCAN_BLK];
    int t = threadIdx.x;
    int gid = blockIdx.x * SCAN_BLK + t;
    sh[t] = g_count[gid];
    __syncthreads();
    #pragma unroll
    for (int off = 1; off < SCAN_BLK; off <<= 1) {
        int v = (t >= off) ? sh[t - off] : 0;
        __syncthreads();
        sh[t] += v;
        __syncthreads();
    }
    g_off[gid + 1] = sh[t];
    if (t == SCAN_BLK - 1) g_blksum[blockIdx.x] = sh[t];
}

// ---------------- K2b: scan block sums (single block) ----------------
__global__ void scanB_kernel() {
    __shared__ int sh[SCAN_NBLK];
    int t = threadIdx.x;
    sh[t] = g_blksum[t];
    __syncthreads();
    #pragma unroll
    for (int off = 1; off < SCAN_NBLK; off <<= 1) {
        int v = (t >= off) ? sh[t - off] : 0;
        __syncthreads();
        sh[t] += v;
        __syncthreads();
    }
    g_blksum[t] = sh[t];
}

// ---------------- K2c: add block prefixes ----------------
__global__ void scanC_kernel() {
    int gid = blockIdx.x * SCAN_BLK + threadIdx.x;
    int b = blockIdx.x;
    int add = (b == 0) ? 0 : g_blksum[b - 1];
    g_off[gid + 1] += add;
}

// ---------------- K2d: init scatter cursor = exclusive offset ----------------
__global__ void cursor_kernel() {
    int gid = blockIdx.x * blockDim.x + threadIdx.x;
    if (gid < TOTC) g_count[gid] = g_off[gid];
}

// ---------------- K3: scatter points into cell-sorted order ----------------
__global__ void scatter_kernel(const float* __restrict__ src_coords,
                               const float* __restrict__ tgt_coords) {
    int u = blockIdx.x * blockDim.x + threadIdx.x;
    if (u >= 2 * NPTS) return;
    int side = u >> 15;
    int i = u & (NPTS - 1);
    const float* c = side ? tgt_coords : src_coords;
    float x = c[3 * i], y = c[3 * i + 1], z = c[3 * i + 2];
    int cell = side * G3 + (cell_of(z) * G + cell_of(y)) * G + cell_of(x);
    int pos = atomicAdd(&g_count[cell], 1);
    g_pts[pos] = make_float4(x, y, z, __int_as_float(i));
}

// ---------------- K4: shell search for 2nd nearest ----------------
struct Top2 {
    float d1, d2;
    int   i1, i2;
};

__device__ __forceinline__ void scan_range(int s, int e,
                                           float qx, float qy, float qz,
                                           Top2& t) {
    for (int i = s; i < e; i++) {
        float4 p = g_pts[i];
        float dx = qx - p.x, dy = qy - p.y, dz = qz - p.z;
        float d = fmaf(dx, dx, fmaf(dy, dy, dz * dz));
        if (d < t.d2) {
            int j = __float_as_int(p.w);
            if (d < t.d1) {
                t.d2 = t.d1; t.i2 = t.i1;
                t.d1 = d;    t.i1 = j;
            } else {
                t.d2 = d;    t.i2 = j;
            }
        }
    }
}

__global__ void search_kernel(const float* __restrict__ src_sc,
                              const float* __restrict__ tgt_sc) {
    int u = blockIdx.x * blockDim.x + threadIdx.x;
    if (u >= 2 * MQ) return;
    int side = u >> 13;
    int q = u & (MQ - 1);
    const float* sc = side ? tgt_sc : src_sc;
    float qx = sc[3 * q], qy = sc[3 * q + 1], qz = sc[3 * q + 2];
    int cx = cell_of(qx), cy = cell_of(qy), cz = cell_of(qz);
    int sbase = side * G3;

    Top2 t;
    t.d1 = FLT_MAX; t.d2 = FLT_MAX; t.i1 = -1; t.i2 = -1;

    for (int r = 0; r <= G; r++) {
        int zlo = max(cz - r, 0), zhi = min(cz + r, G - 1);
        int ylo = max(cy - r, 0), yhi = min(cy + r, G - 1);
        int xlo = max(cx - r, 0), xhi = min(cx + r, G - 1);
        for (int z = zlo; z <= zhi; z++) {
            bool zface = (z == cz - r) || (z == cz + r);
            for (int y = ylo; y <= yhi; y++) {
                bool yface = (y == cy - r) || (y == cy + r);
                int rowbase = sbase + (z * G + y) * G;
                if (zface || yface) {
                    // full x run — cells contiguous, merge into one range
                    int s = g_off[rowbase + xlo];
                    int e = g_off[rowbase + xhi + 1];
                    scan_range(s, e, qx, qy, qz, t);
                } else {
                    // interior row: only the two x-faces
                    int xa = cx - r;
                    if (xa >= 0) {
                        int s = g_off[rowbase + xa];
                        int e = g_off[rowbase + xa + 1];
                        scan_range(s, e, qx, qy, qz, t);
                    }
                    int xb = cx + r;
                    if (xb <= G - 1) {
                        int s = g_off[rowbase + xb];
                        int e = g_off[rowbase + xb + 1];
                        scan_range(s, e, qx, qy, qz, t);
                    }
                }
            }
        }
        // after completing shell r, every unscanned point is at distance >= r*H
        float bnd = (float)r * HCELL;
        if (bnd * bnd >= t.d2) break;
    }

    g_idx2[side][q] = t.i2;
}

// ---------------- K5: gather features ----------------
__global__ void gather_kernel(const float* __restrict__ src_feat,
                              const float* __restrict__ tgt_feat,
                              float* __restrict__ out) {
    int row = blockIdx.x;                 // 0 .. 2*MQ-1
    int side = (row >= MQ) ? 1 : 0;
    int q = side ? (row - MQ) : row;
    const float* f = side ? tgt_feat : src_feat;
    int idx = g_idx2[side][q];
    const float4* srcp = (const float4*)(f + (size_t)idx * CF);
    float4* dstp = (float4*)(out + (size_t)row * CF);
    dstp[threadIdx.x] = srcp[threadIdx.x];
}

extern "C" void kernel_launch(void* const* d_in, const int* in_sizes, int n_in,
                              void* d_out, int out_size) {
    const float* src        = (const float*)d_in[0];   // [N, C]
    const float* tgt        = (const float*)d_in[1];   // [N, C]
    const float* src_coords = (const float*)d_in[2];   // [N, 3]
    const float* tgt_coords = (const float*)d_in[3];   // [N, 3]
    const float* src_sc     = (const float*)d_in[4];   // [M, 3]
    const float* tgt_sc     = (const float*)d_in[5];   // [M, 3]
    float* out = (float*)d_out;                        // [2*M, C]

    zero_kernel<<<(TOTC + 255) / 256, 256>>>();
    hist_kernel<<<(2 * NPTS + 255) / 256, 256>>>(src_coords, tgt_coords);
    scanA_kernel<<<SCAN_NBLK, SCAN_BLK>>>();
    scanB_kernel<<<1, SCAN_NBLK>>>();
    scanC_kernel<<<SCAN_NBLK, SCAN_BLK>>>();
    cursor_kernel<<<(TOTC + 255) / 256, 256>>>();
    scatter_kernel<<<(2 * NPTS + 255) / 256, 256>>>(src_coords, tgt_coords);
    search_kernel<<<(2 * MQ + 127) / 128, 128>>>(src_sc, tgt_sc);
    gather_kernel<<<2 * MQ, CF / 4>>>(src, tgt, out);
}